// round 14
// baseline (speedup 1.0000x reference)
#include <cuda_runtime.h>
#include <cuda_fp16.h>
#include <cstdint>

// ---------------------------------------------------------------------------
// N=10000, D=512, K=20 (keep top-21 per row).
//   h = normalize(relu(f*w0)*w1) -> fp16 (GEMM) + fp32 (exact boundary dots)
//   sim = h16*h16^T (mma.sync m16n8k16, FP32 accum — legacy-rate floor),
//   stored fp16 in g_sim.  Per row (512 thr): 2-pass radix select on 16-bit
//   keys, sure-keep if s > t21+DELTA; band re-ranked with exact fp32 dots
//   (jax ties).  Others -> e^-6.  Diagonal pinned to exactly 1.0.
// ---------------------------------------------------------------------------

#define MAXN 10240
#define DIM  512
#define KKEEP 21
#define DELTA 4e-4f
#define BANDCAP 256

__device__ __half g_h[MAXN * DIM];
__device__ float  g_hf[MAXN * DIM];
__device__ __half g_sim[MAXN * MAXN];   // ~210 MB scratch

__device__ __forceinline__ uint32_t smem_u32(const void* p) {
    uint32_t a;
    asm("{ .reg .u64 t; cvta.to.shared.u64 t, %1; cvt.u32.u64 %0, t; }"
        : "=r"(a) : "l"(p));
    return a;
}
#define SWZ(o) ((o) ^ (((o) >> 3) & 0x70))

__device__ __forceinline__ unsigned o16(unsigned h) {
    return (h & 0x8000u) ? (~h & 0xFFFFu) : (h | 0x8000u);
}

// ------------------------- kernel 1: diag MLP + L2 normalize ---------------
__global__ __launch_bounds__(128) void norm_kernel(
    const float* __restrict__ f, const float* __restrict__ w0,
    const float* __restrict__ w1, int N)
{
    int row = blockIdx.x;
    if (row >= N) return;
    const float* fr = f + (size_t)row * DIM;
    float v[4];
    int t = threadIdx.x;
    float ss = 0.f;
#pragma unroll
    for (int i = 0; i < 4; i++) {
        int c = t + i * 128;
        float x = fr[c] * w0[c];
        x = x > 0.f ? x : 0.f;
        x *= w1[c];
        v[i] = x;
        ss += x * x;
    }
    __shared__ float red[4];
#pragma unroll
    for (int o = 16; o > 0; o >>= 1) ss += __shfl_xor_sync(0xffffffffu, ss, o);
    if ((t & 31) == 0) red[t >> 5] = ss;
    __syncthreads();
    float tot = red[0] + red[1] + red[2] + red[3];
    float inv = 1.0f / fmaxf(sqrtf(tot), 1e-12f);
#pragma unroll
    for (int i = 0; i < 4; i++) {
        int c = t + i * 128;
        float x = v[i] * inv;
        g_h[(size_t)row * DIM + c]  = __float2half_rn(x);
        g_hf[(size_t)row * DIM + c] = x;
    }
}

// ------------------------- kernel 2: mma.sync fp16 GEMM (fp32 acc) ---------
#define KC 64
#define A_STG 16384
#define STG 32768
#define NCHUNK 8
#define CS_PITCH 129
#define GEMM_SMEM (128 * CS_PITCH * 4 + 256)   // 66304 >= 2*STG; Cs overlay

#define LDSMX4(r0, r1, r2, r3, a) \
    asm volatile("ldmatrix.sync.aligned.m8n8.x4.shared.b16 {%0,%1,%2,%3}, [%4];" \
        : "=r"(r0), "=r"(r1), "=r"(r2), "=r"(r3) : "r"(a))

#define MMA16816(d, a, b0, b1) \
    asm volatile("mma.sync.aligned.m16n8k16.row.col.f32.f16.f16.f32 " \
        "{%0,%1,%2,%3}, {%4,%5,%6,%7}, {%8,%9}, {%0,%1,%2,%3};" \
        : "+f"((d)[0]), "+f"((d)[1]), "+f"((d)[2]), "+f"((d)[3]) \
        : "r"((a)[0]), "r"((a)[1]), "r"((a)[2]), "r"((a)[3]), "r"(b0), "r"(b1))

__global__ __launch_bounds__(256, 2) void gemm_mma(int N)
{
    extern __shared__ char smem[];
    const uint32_t sb = smem_u32(smem);

    int x = blockIdx.x;
    int bi = (int)((sqrtf(8.f * (float)x + 1.f) - 1.f) * 0.5f);
    while ((bi + 1) * (bi + 2) / 2 <= x) bi++;
    while (bi * (bi + 1) / 2 > x) bi--;
    const int bj = x - bi * (bi + 1) / 2;
    const int bm = bi * 128;
    const int bn = bj * 128;

    const int tid = threadIdx.x;
    const int lane = tid & 31;
    const int wid = tid >> 5;
    const int wm = wid & 3;
    const int wn = wid >> 2;

    float acc[2][8][4];
#pragma unroll
    for (int mi = 0; mi < 2; mi++)
#pragma unroll
        for (int ni = 0; ni < 8; ni++)
#pragma unroll
            for (int q = 0; q < 4; q++) acc[mi][ni][q] = 0.f;

    const int g = lane >> 3;
    const int arow = wm * 32 + ((g & 1) * 8) + (lane & 7);
    const int akb = (g >> 1) * 16;
    const int brow = wn * 64 + ((g >> 1) * 8) + (lane & 7);
    const int bkb = (g & 1) * 16;

#define ISSUE_CHUNK(ch) do {                                                  \
    int kc_ = (ch) * KC;                                                      \
    uint32_t base_ = sb + ((ch) & 1) * STG;                                   \
    _Pragma("unroll")                                                         \
    for (int i_ = 0; i_ < 8; i_++) {                                          \
        int ci_ = tid + i_ * 256;                                             \
        int isB_ = ci_ >> 10;                                                 \
        int cj_ = ci_ & 1023;                                                 \
        int r_ = cj_ >> 3, c_ = cj_ & 7;                                      \
        int grow_ = (isB_ ? bn : bm) + r_;                                    \
        uint32_t dst_ = base_ + isB_ * A_STG + SWZ(r_ * 128 + c_ * 16);       \
        const void* src_ = g_h + (size_t)grow_ * DIM + kc_ + c_ * 8;          \
        asm volatile("cp.async.cg.shared.global [%0], [%1], 16;"              \
                     :: "r"(dst_), "l"(src_) : "memory");                     \
    }                                                                         \
    asm volatile("cp.async.commit_group;" ::: "memory");                      \
} while (0)

    ISSUE_CHUNK(0);
    for (int ch = 0; ch < NCHUNK; ch++) {
        if (ch + 1 < NCHUNK) {
            ISSUE_CHUNK(ch + 1);
            asm volatile("cp.async.wait_group 1;" ::: "memory");
        } else {
            asm volatile("cp.async.wait_group 0;" ::: "memory");
        }
        __syncthreads();

        const uint32_t Ab = sb + (ch & 1) * STG;
        const uint32_t Bb = Ab + A_STG;
#pragma unroll
        for (int kk = 0; kk < 4; kk++) {
            uint32_t a[2][4];
#pragma unroll
            for (int mi = 0; mi < 2; mi++) {
                uint32_t addr = Ab + SWZ((arow + mi * 16) * 128 + kk * 32 + akb);
                LDSMX4(a[mi][0], a[mi][1], a[mi][2], a[mi][3], addr);
            }
            uint32_t b[4][4];
#pragma unroll
            for (int p = 0; p < 4; p++) {
                uint32_t addr = Bb + SWZ((brow + p * 16) * 128 + kk * 32 + bkb);
                LDSMX4(b[p][0], b[p][1], b[p][2], b[p][3], addr);
            }
#pragma unroll
            for (int mi = 0; mi < 2; mi++)
#pragma unroll
                for (int ni = 0; ni < 8; ni++)
                    MMA16816(acc[mi][ni], a[mi], b[ni >> 1][(ni & 1) * 2],
                             b[ni >> 1][(ni & 1) * 2 + 1]);
        }
        __syncthreads();
    }

    // epilogue: stage fp32 to smem, store fp16 (half2) to g_sim (+mirror)
    float* Cs = (float*)smem;
    {
        const int r0 = wm * 32 + (lane >> 2);
        const int c0 = wn * 64 + 2 * (lane & 3);
#pragma unroll
        for (int mi = 0; mi < 2; mi++)
#pragma unroll
            for (int ni = 0; ni < 8; ni++) {
                int rr = r0 + mi * 16;
                int cc = c0 + ni * 8;
                Cs[rr * CS_PITCH + cc]           = acc[mi][ni][0];
                Cs[rr * CS_PITCH + cc + 1]       = acc[mi][ni][1];
                Cs[(rr + 8) * CS_PITCH + cc]     = acc[mi][ni][2];
                Cs[(rr + 8) * CS_PITCH + cc + 1] = acc[mi][ni][3];
            }
    }
    __syncthreads();

    {
        const int c2 = (tid & 63) * 2;
        const int rh = tid >> 6;            // 0..3
#pragma unroll 4
        for (int it = 0; it < 32; it++) {
            int r = it * 4 + rh;
            int gr = bm + r, gc = bn + c2;
            if (gr < N && gc + 1 < N) {
                __half2 hv = __floats2half2_rn(Cs[r * CS_PITCH + c2],
                                               Cs[r * CS_PITCH + c2 + 1]);
                *reinterpret_cast<__half2*>(&g_sim[(size_t)gr * N + gc]) = hv;
            }
        }
    }
    if (bi != bj) {
        const int r2 = (tid & 63) * 2;
        const int ch2 = tid >> 6;
#pragma unroll 4
        for (int it = 0; it < 32; it++) {
            int c = it * 4 + ch2;
            int gr = bn + c, gcb = bm + r2;
            if (gr < N && gcb + 1 < N) {
                __half2 hv = __floats2half2_rn(Cs[r2 * CS_PITCH + c],
                                               Cs[(r2 + 1) * CS_PITCH + c]);
                *reinterpret_cast<__half2*>(&g_sim[(size_t)gr * N + gcb]) = hv;
            }
        }
    }
}

// --------- kernel 3: top-21 (16-bit radix + exact-fp32 boundary) -----------
// 512 threads/block.  dyn smem: srow u16[10240] @0 (20480) | hrow f[512]
// @20480 | bval f[256] @22528 | bidx i[256] @23552 | hist i[256] @24576 |
// selv f[24] @25600 | seli i[24] @25696 | ctrl i[8] @25792  => 25824
#define TOPK_SMEM 25856
#define TKT 512

__global__ __launch_bounds__(TKT) void topk_kernel(float* __restrict__ Out, int N)
{
    extern __shared__ char sm[];
    unsigned short* srow = (unsigned short*)sm;
    float* hrow = (float*)(sm + 20480);
    float* bval = (float*)(sm + 22528);
    int*   bidx = (int*)(sm + 23552);
    int*   hist = (int*)(sm + 24576);
    float* selv = (float*)(sm + 25600);
    int*   seli = (int*)(sm + 25696);
    int*   ctrl = (int*)(sm + 25792);

    const int row = blockIdx.x;
    const int t = threadIdx.x;
    float* rowp = Out + (size_t)row * N;
    const int iters = (N + TKT - 1) / TKT;

    // vector load of fp16 sim row (streaming: evict-first)
    {
        const uint4* src = (const uint4*)(g_sim + (size_t)row * N);
        const int nv = N / 8;               // 1250
        for (int i = t; i < nv; i += TKT) {
            uint4 v;
            asm volatile("ld.global.cs.v4.u32 {%0,%1,%2,%3}, [%4];"
                         : "=r"(v.x), "=r"(v.y), "=r"(v.z), "=r"(v.w)
                         : "l"(src + i));
            ((uint4*)srow)[i] = v;
        }
    }
    for (int i = t; i < DIM; i += TKT) hrow[i] = g_hf[(size_t)row * DIM + i];
    if (t == 0) {
        srow[row] = 0x3C00;                 // pin diagonal to exactly 1.0
        ctrl[2] = 0; ctrl[3] = 0;
    }
    if (t < 256) hist[t] = 0;
    __syncthreads();

    // ---- radix pass 0: high byte of 16-bit ordered key ----
    for (int it = 0; it < iters; it++) {
        int j = t + it * TKT;
        bool pred = (j < N);
        unsigned act = __ballot_sync(0xffffffffu, pred);
        if (pred) {
            int bin = (int)(o16(srow[j]) >> 8);
            unsigned same = __match_any_sync(act, bin);
            if ((__ffs(same) - 1) == (t & 31))
                atomicAdd(&hist[bin], __popc(same));
        }
    }
    __syncthreads();
    if (t == 0) {
        int cum = 0, b = 255;
        for (; b >= 0; b--) { cum += hist[b]; if (cum >= KKEEP) break; }
        ctrl[0] = b;
        ctrl[1] = KKEEP - (cum - hist[b]);
    }
    __syncthreads();
    const int b0 = ctrl[0];
    int need = ctrl[1];
    if (t < 256) hist[t] = 0;
    __syncthreads();

    // ---- radix pass 1: low byte within prefix b0 ----
    for (int it = 0; it < iters; it++) {
        int j = t + it * TKT;
        unsigned key = (j < N) ? o16(srow[j]) : 0u;
        bool pred = (j < N) && ((int)(key >> 8) == b0);
        unsigned act = __ballot_sync(0xffffffffu, pred);
        if (pred) {
            int bin = (int)(key & 255u);
            unsigned same = __match_any_sync(act, bin);
            if ((__ffs(same) - 1) == (t & 31))
                atomicAdd(&hist[bin], __popc(same));
        }
    }
    __syncthreads();
    if (t == 0) {
        int cum = 0, b = 255;
        for (; b >= 0; b--) { cum += hist[b]; if (cum >= need) break; }
        ctrl[0] = (b0 << 8) | b;
    }
    __syncthreads();
    const unsigned t21key = (unsigned)ctrl[0];
    const unsigned short t21h = (unsigned short)((t21key & 0x8000u)
                                ? (t21key & 0x7FFFu) : (~t21key & 0xFFFFu));
    const float t21f = __half2float(__ushort_as_half(t21h));
    const float hi_thr = t21f + DELTA;
    const float lo_thr = t21f - DELTA;

    // ---- count sure-keeps; compact boundary band ----
    {
        int lc = 0;
        for (int j = t; j < N; j += TKT) {
            float s = __half2float(__ushort_as_half(srow[j]));
            if (s > hi_thr) lc++;
            else if (s >= lo_thr) {
                int p = atomicAdd(&ctrl[3], 1);
                if (p < BANDCAP) bidx[p] = j;
            }
        }
#pragma unroll
        for (int o = 16; o > 0; o >>= 1) lc += __shfl_xor_sync(0xffffffffu, lc, o);
        if ((t & 31) == 0 && lc) atomicAdd(&ctrl[2], lc);
    }
    __syncthreads();
    const int nb = min(ctrl[3], BANDCAP);
    int need_band = KKEEP - ctrl[2];
    if (need_band > nb) need_band = nb;
    if (need_band < 0) need_band = 0;

    // ---- exact fp32 dots for band members (warp per member) ----
    {
        const int wwid = t >> 5, lane = t & 31;
        for (int ci = wwid; ci < nb; ci += (TKT / 32)) {
            const float* hj = g_hf + (size_t)bidx[ci] * DIM;
            float s = 0.f;
#pragma unroll
            for (int d = lane; d < DIM; d += 32) s += hrow[d] * hj[d];
#pragma unroll
            for (int o = 16; o > 0; o >>= 1) s += __shfl_xor_sync(0xffffffffu, s, o);
            if (lane == 0) bval[ci] = s;
        }
    }
    __syncthreads();

    // ---- serial select need_band best by (exact val desc, idx asc) ----
    if (t == 0) {
        int nsel = 0;
        for (int k = 0; k < need_band; k++) {
            int best = -1;
            float bv = 0.f; int bix = 0x7fffffff;
            for (int i = 0; i < nb; i++) {
                float v = bval[i];
                if (v == -3.0e38f) continue;
                int ix = bidx[i];
                if (best < 0 || v > bv || (v == bv && ix < bix)) {
                    best = i; bv = v; bix = ix;
                }
            }
            if (best < 0) break;
            seli[nsel] = bidx[best];
            selv[nsel] = bval[best];
            nsel++;
            bval[best] = -3.0e38f;
        }
        ctrl[4] = nsel;
    }
    __syncthreads();

    // ---- write output (float4, streaming), then patch band selections ----
    const float CBASE = expf(-6.0f);
    for (int j0 = t * 4; j0 < N; j0 += TKT * 4) {
        float4 o;
        float* op = (float*)&o;
#pragma unroll
        for (int q = 0; q < 4; q++) {
            float s = __half2float(__ushort_as_half(srow[j0 + q]));
            if (s > hi_thr) {
                float xx = 6.0f * s - 6.0f;
                op[q] = (xx > 0.f) ? (xx + 1.0f) : expf(xx);
            } else {
                op[q] = CBASE;
            }
        }
        asm volatile("st.global.cs.v4.f32 [%0], {%1,%2,%3,%4};"
                     :: "l"(rowp + j0), "f"(o.x), "f"(o.y), "f"(o.z), "f"(o.w));
    }
    __syncthreads();
    if (t < ctrl[4]) {
        float v = selv[t];
        float xx = 6.0f * v - 6.0f;
        rowp[seli[t]] = (xx > 0.f) ? (xx + 1.0f) : expf(xx);
    }
}

// ---------------------------------------------------------------------------
extern "C" void kernel_launch(void* const* d_in, const int* in_sizes, int n_in,
                              void* d_out, int out_size)
{
    const float* features = (const float*)d_in[0];
    const float* w0 = (const float*)d_in[1];
    const float* w1 = (const float*)d_in[2];
    float* out = (float*)d_out;

    int D = in_sizes[1];           // 512
    int N = in_sizes[0] / D;       // 10000
    (void)n_in; (void)out_size;

    norm_kernel<<<N, 128>>>(features, w0, w1, N);

    int nb = (N + 127) / 128;
    int npairs = nb * (nb + 1) / 2;
    cudaFuncSetAttribute(gemm_mma, cudaFuncAttributeMaxDynamicSharedMemorySize, GEMM_SMEM);
    gemm_mma<<<npairs, 256, GEMM_SMEM>>>(N);

    cudaFuncSetAttribute(topk_kernel, cudaFuncAttributeMaxDynamicSharedMemorySize, TOPK_SMEM);
    topk_kernel<<<N, TKT, TOPK_SMEM>>>(out, N);
}

// round 16
// speedup vs baseline: 1.1665x; 1.1665x over previous
#include <cuda_runtime.h>
#include <cuda_fp16.h>
#include <cstdint>

// ---------------------------------------------------------------------------
// N=10000, D=512, K=20 (keep top-21 per row).
//   h = normalize(relu(f*w0)*w1) -> fp16 (GEMM) + fp32 (exact boundary dots)
//   sim = h16*h16^T (mma.sync m16n8k16, fp32 accum), stored fp16 in g_sim.
//   Per row: fused load + radix pass 0, pass 1, on 16-bit keys;
//   sure-keep if s > t21+DELTA; band [t21-DELTA, t21+DELTA] re-ranked with
//   exact fp32 dots (jax ties).  Others -> e^-6.  Diagonal pinned to 1.0.
// ---------------------------------------------------------------------------

#define MAXN 10240
#define DIM  512
#define KKEEP 21
#define DELTA 4e-4f
#define BANDCAP 256

__device__ __half g_h[MAXN * DIM];
__device__ float  g_hf[MAXN * DIM];
__device__ __half g_sim[MAXN * MAXN];   // ~210 MB scratch

__device__ __forceinline__ uint32_t smem_u32(const void* p) {
    uint32_t a;
    asm("{ .reg .u64 t; cvta.to.shared.u64 t, %1; cvt.u32.u64 %0, t; }"
        : "=r"(a) : "l"(p));
    return a;
}
#define SWZ(o) ((o) ^ (((o) >> 3) & 0x70))

__device__ __forceinline__ unsigned o16(unsigned h) {
    return (h & 0x8000u) ? (~h & 0xFFFFu) : (h | 0x8000u);
}

// ------------------------- kernel 1: diag MLP + L2 normalize ---------------
__global__ __launch_bounds__(128) void norm_kernel(
    const float* __restrict__ f, const float* __restrict__ w0,
    const float* __restrict__ w1, int N)
{
    int row = blockIdx.x;
    if (row >= N) return;
    const float* fr = f + (size_t)row * DIM;
    float v[4];
    int t = threadIdx.x;
    float ss = 0.f;
#pragma unroll
    for (int i = 0; i < 4; i++) {
        int c = t + i * 128;
        float x = fr[c] * w0[c];
        x = x > 0.f ? x : 0.f;
        x *= w1[c];
        v[i] = x;
        ss += x * x;
    }
    __shared__ float red[4];
#pragma unroll
    for (int o = 16; o > 0; o >>= 1) ss += __shfl_xor_sync(0xffffffffu, ss, o);
    if ((t & 31) == 0) red[t >> 5] = ss;
    __syncthreads();
    float tot = red[0] + red[1] + red[2] + red[3];
    float inv = 1.0f / fmaxf(sqrtf(tot), 1e-12f);
#pragma unroll
    for (int i = 0; i < 4; i++) {
        int c = t + i * 128;
        float x = v[i] * inv;
        g_h[(size_t)row * DIM + c]  = __float2half_rn(x);
        g_hf[(size_t)row * DIM + c] = x;
    }
}

// ------------------------- kernel 2: mma.sync fp16 GEMM (fp32 acc) ---------
#define KC 64
#define A_STG 16384
#define STG 32768
#define NCHUNK 8
#define CS_PITCH 129
#define GEMM_SMEM (128 * CS_PITCH * 4 + 256)   // 66304 >= 2*STG; Cs overlay

#define LDSMX4(r0, r1, r2, r3, a) \
    asm volatile("ldmatrix.sync.aligned.m8n8.x4.shared.b16 {%0,%1,%2,%3}, [%4];" \
        : "=r"(r0), "=r"(r1), "=r"(r2), "=r"(r3) : "r"(a))

#define MMA16816(d, a, b0, b1) \
    asm volatile("mma.sync.aligned.m16n8k16.row.col.f32.f16.f16.f32 " \
        "{%0,%1,%2,%3}, {%4,%5,%6,%7}, {%8,%9}, {%0,%1,%2,%3};" \
        : "+f"((d)[0]), "+f"((d)[1]), "+f"((d)[2]), "+f"((d)[3]) \
        : "r"((a)[0]), "r"((a)[1]), "r"((a)[2]), "r"((a)[3]), "r"(b0), "r"(b1))

__global__ __launch_bounds__(256, 2) void gemm_mma(int N)
{
    extern __shared__ char smem[];
    const uint32_t sb = smem_u32(smem);

    int x = blockIdx.x;
    int bi = (int)((sqrtf(8.f * (float)x + 1.f) - 1.f) * 0.5f);
    while ((bi + 1) * (bi + 2) / 2 <= x) bi++;
    while (bi * (bi + 1) / 2 > x) bi--;
    const int bj = x - bi * (bi + 1) / 2;
    const int bm = bi * 128;
    const int bn = bj * 128;

    const int tid = threadIdx.x;
    const int lane = tid & 31;
    const int wid = tid >> 5;
    const int wm = wid & 3;
    const int wn = wid >> 2;

    float acc[2][8][4];
#pragma unroll
    for (int mi = 0; mi < 2; mi++)
#pragma unroll
        for (int ni = 0; ni < 8; ni++)
#pragma unroll
            for (int q = 0; q < 4; q++) acc[mi][ni][q] = 0.f;

    const int g = lane >> 3;
    const int arow = wm * 32 + ((g & 1) * 8) + (lane & 7);
    const int akb = (g >> 1) * 16;
    const int brow = wn * 64 + ((g >> 1) * 8) + (lane & 7);
    const int bkb = (g & 1) * 16;

#define ISSUE_CHUNK(ch) do {                                                  \
    int kc_ = (ch) * KC;                                                      \
    uint32_t base_ = sb + ((ch) & 1) * STG;                                   \
    _Pragma("unroll")                                                         \
    for (int i_ = 0; i_ < 8; i_++) {                                          \
        int ci_ = tid + i_ * 256;                                             \
        int isB_ = ci_ >> 10;                                                 \
        int cj_ = ci_ & 1023;                                                 \
        int r_ = cj_ >> 3, c_ = cj_ & 7;                                      \
        int grow_ = (isB_ ? bn : bm) + r_;                                    \
        uint32_t dst_ = base_ + isB_ * A_STG + SWZ(r_ * 128 + c_ * 16);       \
        const void* src_ = g_h + (size_t)grow_ * DIM + kc_ + c_ * 8;          \
        asm volatile("cp.async.cg.shared.global [%0], [%1], 16;"              \
                     :: "r"(dst_), "l"(src_) : "memory");                     \
    }                                                                         \
    asm volatile("cp.async.commit_group;" ::: "memory");                      \
} while (0)

    ISSUE_CHUNK(0);
    for (int ch = 0; ch < NCHUNK; ch++) {
        if (ch + 1 < NCHUNK) {
            ISSUE_CHUNK(ch + 1);
            asm volatile("cp.async.wait_group 1;" ::: "memory");
        } else {
            asm volatile("cp.async.wait_group 0;" ::: "memory");
        }
        __syncthreads();

        const uint32_t Ab = sb + (ch & 1) * STG;
        const uint32_t Bb = Ab + A_STG;
#pragma unroll
        for (int kk = 0; kk < 4; kk++) {
            uint32_t a[2][4];
#pragma unroll
            for (int mi = 0; mi < 2; mi++) {
                uint32_t addr = Ab + SWZ((arow + mi * 16) * 128 + kk * 32 + akb);
                LDSMX4(a[mi][0], a[mi][1], a[mi][2], a[mi][3], addr);
            }
            uint32_t b[4][4];
#pragma unroll
            for (int p = 0; p < 4; p++) {
                uint32_t addr = Bb + SWZ((brow + p * 16) * 128 + kk * 32 + bkb);
                LDSMX4(b[p][0], b[p][1], b[p][2], b[p][3], addr);
            }
#pragma unroll
            for (int mi = 0; mi < 2; mi++)
#pragma unroll
                for (int ni = 0; ni < 8; ni++)
                    MMA16816(acc[mi][ni], a[mi], b[ni >> 1][(ni & 1) * 2],
                             b[ni >> 1][(ni & 1) * 2 + 1]);
        }
        __syncthreads();
    }

    // epilogue: stage fp32 to smem, store fp16 (half2) to g_sim (+mirror)
    float* Cs = (float*)smem;
    {
        const int r0 = wm * 32 + (lane >> 2);
        const int c0 = wn * 64 + 2 * (lane & 3);
#pragma unroll
        for (int mi = 0; mi < 2; mi++)
#pragma unroll
            for (int ni = 0; ni < 8; ni++) {
                int rr = r0 + mi * 16;
                int cc = c0 + ni * 8;
                Cs[rr * CS_PITCH + cc]           = acc[mi][ni][0];
                Cs[rr * CS_PITCH + cc + 1]       = acc[mi][ni][1];
                Cs[(rr + 8) * CS_PITCH + cc]     = acc[mi][ni][2];
                Cs[(rr + 8) * CS_PITCH + cc + 1] = acc[mi][ni][3];
            }
    }
    __syncthreads();

    {
        const int c2 = (tid & 63) * 2;
        const int rh = tid >> 6;            // 0..3
#pragma unroll 4
        for (int it = 0; it < 32; it++) {
            int r = it * 4 + rh;
            int gr = bm + r, gc = bn + c2;
            if (gr < N && gc + 1 < N) {
                __half2 hv = __floats2half2_rn(Cs[r * CS_PITCH + c2],
                                               Cs[r * CS_PITCH + c2 + 1]);
                *reinterpret_cast<__half2*>(&g_sim[(size_t)gr * N + gc]) = hv;
            }
        }
    }
    if (bi != bj) {
        const int r2 = (tid & 63) * 2;
        const int ch2 = tid >> 6;
#pragma unroll 4
        for (int it = 0; it < 32; it++) {
            int c = it * 4 + ch2;
            int gr = bn + c, gcb = bm + r2;
            if (gr < N && gcb + 1 < N) {
                __half2 hv = __floats2half2_rn(Cs[r2 * CS_PITCH + c],
                                               Cs[(r2 + 1) * CS_PITCH + c]);
                *reinterpret_cast<__half2*>(&g_sim[(size_t)gr * N + gcb]) = hv;
            }
        }
    }
}

// --------- kernel 3: top-21 (16-bit radix + exact-fp32 boundary) -----------
// dyn smem: srow u16[10240] @0 (20480) | hrow f[512] @20480 | bval f[256] @22528
//   bidx i[256] @23552 | hist i[256] @24576 | selv f[24] @25600
//   seli i[24] @25696 | ctrl i[8] @25792   => 25824
#define TOPK_SMEM 25856

__global__ __launch_bounds__(256) void topk_kernel(float* __restrict__ Out, int N)
{
    extern __shared__ char sm[];
    unsigned short* srow = (unsigned short*)sm;
    float* hrow = (float*)(sm + 20480);
    float* bval = (float*)(sm + 22528);
    int*   bidx = (int*)(sm + 23552);
    int*   hist = (int*)(sm + 24576);
    float* selv = (float*)(sm + 25600);
    int*   seli = (int*)(sm + 25696);
    int*   ctrl = (int*)(sm + 25792);

    const int row = blockIdx.x;
    const int t = threadIdx.x;
    float* rowp = Out + (size_t)row * N;
    const int iters = (N + 255) / 256;

    for (int i = t; i < DIM; i += 256) hrow[i] = g_hf[(size_t)row * DIM + i];
    if (t == 0) { ctrl[2] = 0; ctrl[3] = 0; }
    hist[t] = 0;
    __syncthreads();

    // ---- fused: vector load of fp16 sim row + diagonal pin + radix pass 0 --
    {
        const uint4* src = (const uint4*)(g_sim + (size_t)row * N);
        const int nv = N / 8;               // 1250
        const int itv = (nv + 255) / 256;   // 5
        for (int it = 0; it < itv; it++) {
            int i = t + it * 256;
            bool pred = (i < nv);
            unsigned act = __ballot_sync(0xffffffffu, pred);
            if (pred) {
                uint4 v = src[i];
                unsigned short* pv = (unsigned short*)&v;
                if ((row >> 3) == i) pv[row & 7] = 0x3C00;  // diag = exactly 1.0
                ((uint4*)srow)[i] = v;
#pragma unroll
                for (int q = 0; q < 8; q++) {
                    int bin = (int)(o16(pv[q]) >> 8);
                    unsigned same = __match_any_sync(act, bin);
                    if ((__ffs(same) - 1) == (t & 31))
                        atomicAdd(&hist[bin], __popc(same));
                }
            }
        }
    }
    __syncthreads();
    if (t == 0) {
        int cum = 0, b = 255;
        for (; b >= 0; b--) { cum += hist[b]; if (cum >= KKEEP) break; }
        ctrl[0] = b;
        ctrl[1] = KKEEP - (cum - hist[b]);
    }
    __syncthreads();
    const int b0 = ctrl[0];
    int need = ctrl[1];
    hist[t] = 0;
    __syncthreads();

    // ---- radix pass 1: low byte within prefix b0 ----
    for (int it = 0; it < iters; it++) {
        int j = t + it * 256;
        unsigned key = (j < N) ? o16(srow[j]) : 0u;
        bool pred = (j < N) && ((int)(key >> 8) == b0);
        unsigned act = __ballot_sync(0xffffffffu, pred);
        if (pred) {
            int bin = (int)(key & 255u);
            unsigned same = __match_any_sync(act, bin);
            if ((__ffs(same) - 1) == (t & 31))
                atomicAdd(&hist[bin], __popc(same));
        }
    }
    __syncthreads();
    if (t == 0) {
        int cum = 0, b = 255;
        for (; b >= 0; b--) { cum += hist[b]; if (cum >= need) break; }
        ctrl[0] = (b0 << 8) | b;
    }
    __syncthreads();
    const unsigned t21key = (unsigned)ctrl[0];
    const unsigned short t21h = (unsigned short)((t21key & 0x8000u)
                                ? (t21key & 0x7FFFu) : (~t21key & 0xFFFFu));
    const float t21f = __half2float(__ushort_as_half(t21h));
    const float hi_thr = t21f + DELTA;
    const float lo_thr = t21f - DELTA;

    // ---- count sure-keeps; compact boundary band ----
    {
        int lc = 0;
        for (int j = t; j < N; j += 256) {
            float s = __half2float(__ushort_as_half(srow[j]));
            if (s > hi_thr) lc++;
            else if (s >= lo_thr) {
                int p = atomicAdd(&ctrl[3], 1);
                if (p < BANDCAP) bidx[p] = j;
            }
        }
#pragma unroll
        for (int o = 16; o > 0; o >>= 1) lc += __shfl_xor_sync(0xffffffffu, lc, o);
        if ((t & 31) == 0 && lc) atomicAdd(&ctrl[2], lc);
    }
    __syncthreads();
    const int nb = min(ctrl[3], BANDCAP);
    int need_band = KKEEP - ctrl[2];
    if (need_band > nb) need_band = nb;
    if (need_band < 0) need_band = 0;

    // ---- exact fp32 dots for band members (warp per member) ----
    {
        const int wwid = t >> 5, lane = t & 31;
        for (int ci = wwid; ci < nb; ci += 8) {
            const float* hj = g_hf + (size_t)bidx[ci] * DIM;
            float s = 0.f;
#pragma unroll
            for (int d = lane; d < DIM; d += 32) s += hrow[d] * hj[d];
#pragma unroll
            for (int o = 16; o > 0; o >>= 1) s += __shfl_xor_sync(0xffffffffu, s, o);
            if (lane == 0) bval[ci] = s;
        }
    }
    __syncthreads();

    // ---- serial select need_band best by (exact val desc, idx asc) ----
    if (t == 0) {
        int nsel = 0;
        for (int k = 0; k < need_band; k++) {
            int best = -1;
            float bv = 0.f; int bix = 0x7fffffff;
            for (int i = 0; i < nb; i++) {
                float v = bval[i];
                if (v == -3.0e38f) continue;
                int ix = bidx[i];
                if (best < 0 || v > bv || (v == bv && ix < bix)) {
                    best = i; bv = v; bix = ix;
                }
            }
            if (best < 0) break;
            seli[nsel] = bidx[best];
            selv[nsel] = bval[best];
            nsel++;
            bval[best] = -3.0e38f;
        }
        ctrl[4] = nsel;
    }
    __syncthreads();

    // ---- write output (float4), then patch exact band selections ----
    const float CBASE = expf(-6.0f);
    for (int j0 = t * 4; j0 < N; j0 += 1024) {
        float4 o;
        float* op = (float*)&o;
#pragma unroll
        for (int q = 0; q < 4; q++) {
            float s = __half2float(__ushort_as_half(srow[j0 + q]));
            if (s > hi_thr) {
                float xx = 6.0f * s - 6.0f;
                op[q] = (xx > 0.f) ? (xx + 1.0f) : expf(xx);
            } else {
                op[q] = CBASE;
            }
        }
        *(float4*)(rowp + j0) = o;
    }
    __syncthreads();
    if (t < ctrl[4]) {
        float v = selv[t];
        float xx = 6.0f * v - 6.0f;
        rowp[seli[t]] = (xx > 0.f) ? (xx + 1.0f) : expf(xx);
    }
}

// ---------------------------------------------------------------------------
extern "C" void kernel_launch(void* const* d_in, const int* in_sizes, int n_in,
                              void* d_out, int out_size)
{
    const float* features = (const float*)d_in[0];
    const float* w0 = (const float*)d_in[1];
    const float* w1 = (const float*)d_in[2];
    float* out = (float*)d_out;

    int D = in_sizes[1];           // 512
    int N = in_sizes[0] / D;       // 10000
    (void)n_in; (void)out_size;

    norm_kernel<<<N, 128>>>(features, w0, w1, N);

    int nb = (N + 127) / 128;
    int npairs = nb * (nb + 1) / 2;
    cudaFuncSetAttribute(gemm_mma, cudaFuncAttributeMaxDynamicSharedMemorySize, GEMM_SMEM);
    gemm_mma<<<npairs, 256, GEMM_SMEM>>>(N);

    cudaFuncSetAttribute(topk_kernel, cudaFuncAttributeMaxDynamicSharedMemorySize, TOPK_SMEM);
    topk_kernel<<<N, 256, TOPK_SMEM>>>(out, N);
}

// round 17
// speedup vs baseline: 1.2015x; 1.0301x over previous
#include <cuda_runtime.h>
#include <cuda_fp16.h>
#include <cstdint>

// ---------------------------------------------------------------------------
// N=10000, D=512, K=20 (keep top-21 per row).
//   h = normalize(relu(f*w0)*w1) -> fp16 (GEMM) + fp32 (exact boundary dots)
//   sim = h16*h16^T (mma.sync m16n8k16, fp32 accum), stored fp16 in g_sim.
//   Per row: fused load + radix pass 0, pass 1 on 16-bit keys; then ONE
//   fused sweep that writes output (elu / e^-6) AND counts sure-keeps AND
//   compacts the band; band re-ranked with exact fp32 dots (jax ties) and
//   selected entries patched.  Diagonal pinned to exactly 1.0.
// ---------------------------------------------------------------------------

#define MAXN 10240
#define DIM  512
#define KKEEP 21
#define DELTA 4e-4f
#define BANDCAP 256

__device__ __half g_h[MAXN * DIM];
__device__ float  g_hf[MAXN * DIM];
__device__ __half g_sim[MAXN * MAXN];   // ~210 MB scratch

__device__ __forceinline__ uint32_t smem_u32(const void* p) {
    uint32_t a;
    asm("{ .reg .u64 t; cvta.to.shared.u64 t, %1; cvt.u32.u64 %0, t; }"
        : "=r"(a) : "l"(p));
    return a;
}
#define SWZ(o) ((o) ^ (((o) >> 3) & 0x70))

__device__ __forceinline__ unsigned o16(unsigned h) {
    return (h & 0x8000u) ? (~h & 0xFFFFu) : (h | 0x8000u);
}

// ------------------------- kernel 1: diag MLP + L2 normalize ---------------
__global__ __launch_bounds__(128) void norm_kernel(
    const float* __restrict__ f, const float* __restrict__ w0,
    const float* __restrict__ w1, int N)
{
    int row = blockIdx.x;
    if (row >= N) return;
    const float* fr = f + (size_t)row * DIM;
    float v[4];
    int t = threadIdx.x;
    float ss = 0.f;
#pragma unroll
    for (int i = 0; i < 4; i++) {
        int c = t + i * 128;
        float x = fr[c] * w0[c];
        x = x > 0.f ? x : 0.f;
        x *= w1[c];
        v[i] = x;
        ss += x * x;
    }
    __shared__ float red[4];
#pragma unroll
    for (int o = 16; o > 0; o >>= 1) ss += __shfl_xor_sync(0xffffffffu, ss, o);
    if ((t & 31) == 0) red[t >> 5] = ss;
    __syncthreads();
    float tot = red[0] + red[1] + red[2] + red[3];
    float inv = 1.0f / fmaxf(sqrtf(tot), 1e-12f);
#pragma unroll
    for (int i = 0; i < 4; i++) {
        int c = t + i * 128;
        float x = v[i] * inv;
        g_h[(size_t)row * DIM + c]  = __float2half_rn(x);
        g_hf[(size_t)row * DIM + c] = x;
    }
}

// ------------------------- kernel 2: mma.sync fp16 GEMM (fp32 acc) ---------
#define KC 64
#define A_STG 16384
#define STG 32768
#define NCHUNK 8
#define CS_PITCH 129
#define GEMM_SMEM (128 * CS_PITCH * 4 + 256)   // 66304 >= 2*STG; Cs overlay

#define LDSMX4(r0, r1, r2, r3, a) \
    asm volatile("ldmatrix.sync.aligned.m8n8.x4.shared.b16 {%0,%1,%2,%3}, [%4];" \
        : "=r"(r0), "=r"(r1), "=r"(r2), "=r"(r3) : "r"(a))

#define MMA16816(d, a, b0, b1) \
    asm volatile("mma.sync.aligned.m16n8k16.row.col.f32.f16.f16.f32 " \
        "{%0,%1,%2,%3}, {%4,%5,%6,%7}, {%8,%9}, {%0,%1,%2,%3};" \
        : "+f"((d)[0]), "+f"((d)[1]), "+f"((d)[2]), "+f"((d)[3]) \
        : "r"((a)[0]), "r"((a)[1]), "r"((a)[2]), "r"((a)[3]), "r"(b0), "r"(b1))

__global__ __launch_bounds__(256, 2) void gemm_mma(int N)
{
    extern __shared__ char smem[];
    const uint32_t sb = smem_u32(smem);

    int x = blockIdx.x;
    int bi = (int)((sqrtf(8.f * (float)x + 1.f) - 1.f) * 0.5f);
    while ((bi + 1) * (bi + 2) / 2 <= x) bi++;
    while (bi * (bi + 1) / 2 > x) bi--;
    const int bj = x - bi * (bi + 1) / 2;
    const int bm = bi * 128;
    const int bn = bj * 128;

    const int tid = threadIdx.x;
    const int lane = tid & 31;
    const int wid = tid >> 5;
    const int wm = wid & 3;
    const int wn = wid >> 2;

    float acc[2][8][4];
#pragma unroll
    for (int mi = 0; mi < 2; mi++)
#pragma unroll
        for (int ni = 0; ni < 8; ni++)
#pragma unroll
            for (int q = 0; q < 4; q++) acc[mi][ni][q] = 0.f;

    const int g = lane >> 3;
    const int arow = wm * 32 + ((g & 1) * 8) + (lane & 7);
    const int akb = (g >> 1) * 16;
    const int brow = wn * 64 + ((g >> 1) * 8) + (lane & 7);
    const int bkb = (g & 1) * 16;

#define ISSUE_CHUNK(ch) do {                                                  \
    int kc_ = (ch) * KC;                                                      \
    uint32_t base_ = sb + ((ch) & 1) * STG;                                   \
    _Pragma("unroll")                                                         \
    for (int i_ = 0; i_ < 8; i_++) {                                          \
        int ci_ = tid + i_ * 256;                                             \
        int isB_ = ci_ >> 10;                                                 \
        int cj_ = ci_ & 1023;                                                 \
        int r_ = cj_ >> 3, c_ = cj_ & 7;                                      \
        int grow_ = (isB_ ? bn : bm) + r_;                                    \
        uint32_t dst_ = base_ + isB_ * A_STG + SWZ(r_ * 128 + c_ * 16);       \
        const void* src_ = g_h + (size_t)grow_ * DIM + kc_ + c_ * 8;          \
        asm volatile("cp.async.cg.shared.global [%0], [%1], 16;"              \
                     :: "r"(dst_), "l"(src_) : "memory");                     \
    }                                                                         \
    asm volatile("cp.async.commit_group;" ::: "memory");                      \
} while (0)

    ISSUE_CHUNK(0);
    for (int ch = 0; ch < NCHUNK; ch++) {
        if (ch + 1 < NCHUNK) {
            ISSUE_CHUNK(ch + 1);
            asm volatile("cp.async.wait_group 1;" ::: "memory");
        } else {
            asm volatile("cp.async.wait_group 0;" ::: "memory");
        }
        __syncthreads();

        const uint32_t Ab = sb + (ch & 1) * STG;
        const uint32_t Bb = Ab + A_STG;
#pragma unroll
        for (int kk = 0; kk < 4; kk++) {
            uint32_t a[2][4];
#pragma unroll
            for (int mi = 0; mi < 2; mi++) {
                uint32_t addr = Ab + SWZ((arow + mi * 16) * 128 + kk * 32 + akb);
                LDSMX4(a[mi][0], a[mi][1], a[mi][2], a[mi][3], addr);
            }
            uint32_t b[4][4];
#pragma unroll
            for (int p = 0; p < 4; p++) {
                uint32_t addr = Bb + SWZ((brow + p * 16) * 128 + kk * 32 + bkb);
                LDSMX4(b[p][0], b[p][1], b[p][2], b[p][3], addr);
            }
#pragma unroll
            for (int mi = 0; mi < 2; mi++)
#pragma unroll
                for (int ni = 0; ni < 8; ni++)
                    MMA16816(acc[mi][ni], a[mi], b[ni >> 1][(ni & 1) * 2],
                             b[ni >> 1][(ni & 1) * 2 + 1]);
        }
        __syncthreads();
    }

    // epilogue: stage fp32 to smem, store fp16 (half2) to g_sim (+mirror)
    float* Cs = (float*)smem;
    {
        const int r0 = wm * 32 + (lane >> 2);
        const int c0 = wn * 64 + 2 * (lane & 3);
#pragma unroll
        for (int mi = 0; mi < 2; mi++)
#pragma unroll
            for (int ni = 0; ni < 8; ni++) {
                int rr = r0 + mi * 16;
                int cc = c0 + ni * 8;
                Cs[rr * CS_PITCH + cc]           = acc[mi][ni][0];
                Cs[rr * CS_PITCH + cc + 1]       = acc[mi][ni][1];
                Cs[(rr + 8) * CS_PITCH + cc]     = acc[mi][ni][2];
                Cs[(rr + 8) * CS_PITCH + cc + 1] = acc[mi][ni][3];
            }
    }
    __syncthreads();

    {
        const int c2 = (tid & 63) * 2;
        const int rh = tid >> 6;            // 0..3
#pragma unroll 4
        for (int it = 0; it < 32; it++) {
            int r = it * 4 + rh;
            int gr = bm + r, gc = bn + c2;
            if (gr < N && gc + 1 < N) {
                __half2 hv = __floats2half2_rn(Cs[r * CS_PITCH + c2],
                                               Cs[r * CS_PITCH + c2 + 1]);
                *reinterpret_cast<__half2*>(&g_sim[(size_t)gr * N + gc]) = hv;
            }
        }
    }
    if (bi != bj) {
        const int r2 = (tid & 63) * 2;
        const int ch2 = tid >> 6;
#pragma unroll 4
        for (int it = 0; it < 32; it++) {
            int c = it * 4 + ch2;
            int gr = bn + c, gcb = bm + r2;
            if (gr < N && gcb + 1 < N) {
                __half2 hv = __floats2half2_rn(Cs[r2 * CS_PITCH + c],
                                               Cs[(r2 + 1) * CS_PITCH + c]);
                *reinterpret_cast<__half2*>(&g_sim[(size_t)gr * N + gcb]) = hv;
            }
        }
    }
}

// --------- kernel 3: top-21 (16-bit radix + exact-fp32 boundary) -----------
// dyn smem: srow u16[10240] @0 (20480) | hrow f[512] @20480 | bval f[256] @22528
//   bidx i[256] @23552 | hist i[256] @24576 | selv f[24] @25600
//   seli i[24] @25696 | ctrl i[8] @25792   => 25824
#define TOPK_SMEM 25856

__global__ __launch_bounds__(256) void topk_kernel(float* __restrict__ Out, int N)
{
    extern __shared__ char sm[];
    unsigned short* srow = (unsigned short*)sm;
    float* hrow = (float*)(sm + 20480);
    float* bval = (float*)(sm + 22528);
    int*   bidx = (int*)(sm + 23552);
    int*   hist = (int*)(sm + 24576);
    float* selv = (float*)(sm + 25600);
    int*   seli = (int*)(sm + 25696);
    int*   ctrl = (int*)(sm + 25792);

    const int row = blockIdx.x;
    const int t = threadIdx.x;
    float* rowp = Out + (size_t)row * N;
    const int iters = (N + 255) / 256;

    for (int i = t; i < DIM; i += 256) hrow[i] = g_hf[(size_t)row * DIM + i];
    if (t == 0) { ctrl[2] = 0; ctrl[3] = 0; }
    hist[t] = 0;
    __syncthreads();

    // ---- fused: vector load of fp16 sim row + diagonal pin + radix pass 0 --
    {
        const uint4* src = (const uint4*)(g_sim + (size_t)row * N);
        const int nv = N / 8;               // 1250
        const int itv = (nv + 255) / 256;   // 5
        for (int it = 0; it < itv; it++) {
            int i = t + it * 256;
            bool pred = (i < nv);
            unsigned act = __ballot_sync(0xffffffffu, pred);
            if (pred) {
                uint4 v = src[i];
                unsigned short* pv = (unsigned short*)&v;
                if ((row >> 3) == i) pv[row & 7] = 0x3C00;  // diag = exactly 1.0
                ((uint4*)srow)[i] = v;
#pragma unroll
                for (int q = 0; q < 8; q++) {
                    int bin = (int)(o16(pv[q]) >> 8);
                    unsigned same = __match_any_sync(act, bin);
                    if ((__ffs(same) - 1) == (t & 31))
                        atomicAdd(&hist[bin], __popc(same));
                }
            }
        }
    }
    __syncthreads();
    if (t == 0) {
        int cum = 0, b = 255;
        for (; b >= 0; b--) { cum += hist[b]; if (cum >= KKEEP) break; }
        ctrl[0] = b;
        ctrl[1] = KKEEP - (cum - hist[b]);
    }
    __syncthreads();
    const int b0 = ctrl[0];
    int need = ctrl[1];
    hist[t] = 0;
    __syncthreads();

    // ---- radix pass 1: low byte within prefix b0 ----
    for (int it = 0; it < iters; it++) {
        int j = t + it * 256;
        unsigned key = (j < N) ? o16(srow[j]) : 0u;
        bool pred = (j < N) && ((int)(key >> 8) == b0);
        unsigned act = __ballot_sync(0xffffffffu, pred);
        if (pred) {
            int bin = (int)(key & 255u);
            unsigned same = __match_any_sync(act, bin);
            if ((__ffs(same) - 1) == (t & 31))
                atomicAdd(&hist[bin], __popc(same));
        }
    }
    __syncthreads();
    if (t == 0) {
        int cum = 0, b = 255;
        for (; b >= 0; b--) { cum += hist[b]; if (cum >= need) break; }
        ctrl[0] = (b0 << 8) | b;
    }
    __syncthreads();
    const unsigned t21key = (unsigned)ctrl[0];
    const unsigned short t21h = (unsigned short)((t21key & 0x8000u)
                                ? (t21key & 0x7FFFu) : (~t21key & 0xFFFFu));
    const float t21f = __half2float(__ushort_as_half(t21h));
    const float hi_thr = t21f + DELTA;
    const float lo_thr = t21f - DELTA;

    // ---- FUSED sweep: write output (elu / base) + count sure + compact band
    const float CBASE = expf(-6.0f);
    {
        int lc = 0;
        for (int j0 = t * 4; j0 < N; j0 += 1024) {
            float4 o;
            float* op = (float*)&o;
#pragma unroll
            for (int q = 0; q < 4; q++) {
                float s = __half2float(__ushort_as_half(srow[j0 + q]));
                if (s > hi_thr) {
                    lc++;
                    float xx = 6.0f * s - 6.0f;
                    op[q] = (xx > 0.f) ? (xx + 1.0f) : expf(xx);
                } else {
                    op[q] = CBASE;
                    if (s >= lo_thr) {
                        int p = atomicAdd(&ctrl[3], 1);
                        if (p < BANDCAP) bidx[p] = j0 + q;
                    }
                }
            }
            *(float4*)(rowp + j0) = o;
        }
#pragma unroll
        for (int o = 16; o > 0; o >>= 1) lc += __shfl_xor_sync(0xffffffffu, lc, o);
        if ((t & 31) == 0 && lc) atomicAdd(&ctrl[2], lc);
    }
    __syncthreads();
    const int nb = min(ctrl[3], BANDCAP);
    int need_band = KKEEP - ctrl[2];
    if (need_band > nb) need_band = nb;
    if (need_band < 0) need_band = 0;

    // ---- exact fp32 dots for band members (warp per member) ----
    {
        const int wwid = t >> 5, lane = t & 31;
        for (int ci = wwid; ci < nb; ci += 8) {
            const float* hj = g_hf + (size_t)bidx[ci] * DIM;
            float s = 0.f;
#pragma unroll
            for (int d = lane; d < DIM; d += 32) s += hrow[d] * hj[d];
#pragma unroll
            for (int o = 16; o > 0; o >>= 1) s += __shfl_xor_sync(0xffffffffu, s, o);
            if (lane == 0) bval[ci] = s;
        }
    }
    __syncthreads();

    // ---- serial select need_band best by (exact val desc, idx asc) ----
    if (t == 0) {
        int nsel = 0;
        for (int k = 0; k < need_band; k++) {
            int best = -1;
            float bv = 0.f; int bix = 0x7fffffff;
            for (int i = 0; i < nb; i++) {
                float v = bval[i];
                if (v == -3.0e38f) continue;
                int ix = bidx[i];
                if (best < 0 || v > bv || (v == bv && ix < bix)) {
                    best = i; bv = v; bix = ix;
                }
            }
            if (best < 0) break;
            seli[nsel] = bidx[best];
            selv[nsel] = bval[best];
            nsel++;
            bval[best] = -3.0e38f;
        }
        ctrl[4] = nsel;
    }
    __syncthreads();

    // ---- patch the selected band entries with exact values ----
    if (t < ctrl[4]) {
        float v = selv[t];
        float xx = 6.0f * v - 6.0f;
        rowp[seli[t]] = (xx > 0.f) ? (xx + 1.0f) : expf(xx);
    }
}

// ---------------------------------------------------------------------------
extern "C" void kernel_launch(void* const* d_in, const int* in_sizes, int n_in,
                              void* d_out, int out_size)
{
    const float* features = (const float*)d_in[0];
    const float* w0 = (const float*)d_in[1];
    const float* w1 = (const float*)d_in[2];
    float* out = (float*)d_out;

    int D = in_sizes[1];           // 512
    int N = in_sizes[0] / D;       // 10000
    (void)n_in; (void)out_size;

    norm_kernel<<<N, 128>>>(features, w0, w1, N);

    int nb = (N + 127) / 128;
    int npairs = nb * (nb + 1) / 2;
    cudaFuncSetAttribute(gemm_mma, cudaFuncAttributeMaxDynamicSharedMemorySize, GEMM_SMEM);
    gemm_mma<<<npairs, 256, GEMM_SMEM>>>(N);

    cudaFuncSetAttribute(topk_kernel, cudaFuncAttributeMaxDynamicSharedMemorySize, TOPK_SMEM);
    topk_kernel<<<N, 256, TOPK_SMEM>>>(out, N);
}